// round 1
// baseline (speedup 1.0000x reference)
#include <cuda_runtime.h>

// Output layout (66 floats): trace[64] then gates[2] (tuple flatten order).
//
// Analysis of the reference: the color-refinement trace is independent of x,
// weights, and edge placement — col evolves all-0 -> all-1 -> all-2
// deterministically, mask is always all-true, and sig_mean[new_c] = E/N
// exactly each layer. Hence trace[1] = E/(4N), trace[2] = E/(2N), rest 0.
// gates = sigmoid(alpha_0), sigmoid(alpha_1). The GIN MLP stack is dead code
// with respect to the returned values.

__global__ void bfs_refine_out_kernel(const float* __restrict__ alpha0,
                                      const float* __restrict__ alpha1,
                                      float t1, float t2,
                                      float* __restrict__ out)
{
    int i = threadIdx.x;
    if (i < 64) {
        float v = 0.0f;
        if (i == 1) v = t1;
        if (i == 2) v = t2;
        out[i] = v;
    } else if (i == 64) {
        float a = alpha0[0];
        out[64] = 1.0f / (1.0f + __expf(-a));
    } else if (i == 65) {
        float a = alpha1[0];
        out[65] = 1.0f / (1.0f + __expf(-a));
    }
}

extern "C" void kernel_launch(void* const* d_in, const int* in_sizes, int n_in,
                              void* d_out, int out_size)
{
    // Input order: x, edge_index, W1_0, b1_0, W2_0, b2_0, alpha_0,
    //              W1_1, b1_1, W2_1, b2_1, alpha_1
    const float* alpha0 = (const float*)d_in[6];
    const float* alpha1 = (const float*)d_in[11];

    const long long n_nodes = (long long)in_sizes[0] / 127;  // x is [N, 127]
    const long long n_edges = (long long)in_sizes[1] / 2;    // edge_index is [2, E]

    const double ratio = (double)n_edges / (double)n_nodes;  // E/N
    const float t1 = (float)(ratio * 0.25);  // trace[1] = E/(4N)
    const float t2 = (float)(ratio * 0.5);   // trace[2] = E/(2N)

    float* out = (float*)d_out;
    bfs_refine_out_kernel<<<1, 66>>>(alpha0, alpha1, t1, t2, out);
}